// round 4
// baseline (speedup 1.0000x reference)
#include <cuda_runtime.h>
#include <cuda_bf16.h>

// Problem shape constants (fixed by setup_inputs)
#define DD      512
#define HDIM    64
#define NHEAD   8
#define BATCH   32
#define SEQ     64
#define MBANK   8192
#define NQROWS  (BATCH * SEQ)   // 2048

// Scratch (allocation-free rule: __device__ globals)
__device__ float g_q  [NQROWS * DD];       // 4 MB   q projection
__device__ float g_kv [MBANK * 2 * DD];    // 32 MB  [k | v] projection of bank
__device__ float g_ctx[NQROWS * DD];       // 4 MB   attention context

// ---------------------------------------------------------------------------
// Generic GEMM: C[M,N] = A[M,K] @ W[N,K]^T + bias[N]
// 64x64 tile, 256 threads, 4x4 micro-tile, BK=16, float4 everywhere.
// Requires M,N % 64 == 0 and K % 16 == 0 (true for all uses here).
// ---------------------------------------------------------------------------
__global__ __launch_bounds__(256) void gemm_bias_kernel(
    const float* __restrict__ A, const float* __restrict__ W,
    const float* __restrict__ bias, float* __restrict__ C,
    int M, int N, int K)
{
    __shared__ float As[16][68];   // As[k][m]  (transposed, padded for f4 align)
    __shared__ float Ws[16][68];   // Ws[k][n]

    const int tid = threadIdx.x;
    const int tx  = tid & 15;
    const int ty  = tid >> 4;
    const int bm  = blockIdx.y << 6;
    const int bn  = blockIdx.x << 6;
    const int lr  = tid >> 2;          // 0..63 (tile row loaded by this thread)
    const int lc  = (tid & 3) << 2;    // 0,4,8,12 (k offset, float4)

    float acc[4][4];
#pragma unroll
    for (int i = 0; i < 4; ++i)
#pragma unroll
        for (int j = 0; j < 4; ++j) acc[i][j] = 0.f;

    const float* Ap = A + (size_t)(bm + lr) * K + lc;
    const float* Wp = W + (size_t)(bn + lr) * K + lc;

    for (int k0 = 0; k0 < K; k0 += 16) {
        float4 av = *(const float4*)(Ap + k0);
        float4 wv = *(const float4*)(Wp + k0);
        __syncthreads();
        As[lc + 0][lr] = av.x; As[lc + 1][lr] = av.y;
        As[lc + 2][lr] = av.z; As[lc + 3][lr] = av.w;
        Ws[lc + 0][lr] = wv.x; Ws[lc + 1][lr] = wv.y;
        Ws[lc + 2][lr] = wv.z; Ws[lc + 3][lr] = wv.w;
        __syncthreads();
#pragma unroll
        for (int kk = 0; kk < 16; ++kk) {
            float4 a4 = *(const float4*)&As[kk][ty << 2];
            float4 b4 = *(const float4*)&Ws[kk][tx << 2];
            float a[4] = {a4.x, a4.y, a4.z, a4.w};
            float b[4] = {b4.x, b4.y, b4.z, b4.w};
#pragma unroll
            for (int i = 0; i < 4; ++i)
#pragma unroll
                for (int j = 0; j < 4; ++j)
                    acc[i][j] = fmaf(a[i], b[j], acc[i][j]);
        }
    }

    float4 bv = *(const float4*)&bias[bn + (tx << 2)];
    float bb[4] = {bv.x, bv.y, bv.z, bv.w};
#pragma unroll
    for (int i = 0; i < 4; ++i) {
        float4 o;
        o.x = acc[i][0] + bb[0];
        o.y = acc[i][1] + bb[1];
        o.z = acc[i][2] + bb[2];
        o.w = acc[i][3] + bb[3];
        *(float4*)&C[(size_t)(bm + (ty << 2) + i) * N + bn + (tx << 2)] = o;
    }
}

// ---------------------------------------------------------------------------
// Flash attention: one block per (b, h). S=64 q rows, hd=64, M=8192 keys in
// chunks of 64. Online softmax, fp32 accumulation.
// Dynamic smem: qt[64][68] (d-major, pre-scaled), kt[64][68] (d-major),
//               vs[64][68] (key-major), ps[64][68] (row-major probs).
// ---------------------------------------------------------------------------
__global__ __launch_bounds__(256) void attn_kernel(
    const float* __restrict__ qb, const float* __restrict__ kvb,
    float* __restrict__ ctx)
{
    extern __shared__ float smdyn[];
    float* qt = smdyn;                 // qt[d*68 + r]
    float* kt = smdyn + 64 * 68;       // kt[d*68 + j]
    float* vs = smdyn + 2 * 64 * 68;   // vs[j*68 + c]
    float* ps = smdyn + 3 * 64 * 68;   // ps[r*68 + j]

    const int tid = threadIdx.x;
    const int tx  = tid & 15;
    const int ty  = tid >> 4;
    const int b   = blockIdx.x >> 3;
    const int h   = blockIdx.x & 7;
    const float scale = 0.125f;   // 1/sqrt(64)

    // Load q tile (64x64), scaled, stored d-major (transposed)
#pragma unroll
    for (int t = 0; t < 4; ++t) {
        int idx = tid + (t << 8);
        int r   = idx >> 4;
        int d4  = (idx & 15) << 2;
        float4 v = *(const float4*)&qb[(size_t)(b * SEQ + r) * DD + h * HDIM + d4];
        qt[(d4 + 0) * 68 + r] = v.x * scale;
        qt[(d4 + 1) * 68 + r] = v.y * scale;
        qt[(d4 + 2) * 68 + r] = v.z * scale;
        qt[(d4 + 3) * 68 + r] = v.w * scale;
    }

    float m[4], l[4], o[4][4];
#pragma unroll
    for (int i = 0; i < 4; ++i) {
        m[i] = -1e30f; l[i] = 0.f;
#pragma unroll
        for (int j = 0; j < 4; ++j) o[i][j] = 0.f;
    }

    for (int j0 = 0; j0 < MBANK; j0 += 64) {
        // Prefetch K/V chunk into registers (overlaps with the barrier)
        float4 kr[4], vr[4];
#pragma unroll
        for (int t = 0; t < 4; ++t) {
            int idx = tid + (t << 8);
            int j   = idx >> 4;
            int d4  = (idx & 15) << 2;
            const float* base = kvb + (size_t)(j0 + j) * 1024 + h * HDIM + d4;
            kr[t] = *(const float4*)base;
            vr[t] = *(const float4*)(base + 512);
        }
        __syncthreads();   // prior iteration's reads of kt/vs/ps are done
#pragma unroll
        for (int t = 0; t < 4; ++t) {
            int idx = tid + (t << 8);
            int j   = idx >> 4;
            int d4  = (idx & 15) << 2;
            kt[(d4 + 0) * 68 + j] = kr[t].x;
            kt[(d4 + 1) * 68 + j] = kr[t].y;
            kt[(d4 + 2) * 68 + j] = kr[t].z;
            kt[(d4 + 3) * 68 + j] = kr[t].w;
            *(float4*)&vs[j * 68 + d4] = vr[t];
        }
        __syncthreads();

        // Scores s[i][j] for q rows ty*4+i, keys tx*4+j
        float s[4][4];
#pragma unroll
        for (int i = 0; i < 4; ++i)
#pragma unroll
            for (int j = 0; j < 4; ++j) s[i][j] = 0.f;

#pragma unroll 16
        for (int d = 0; d < 64; ++d) {
            float4 a4 = *(const float4*)&qt[d * 68 + (ty << 2)];
            float4 b4 = *(const float4*)&kt[d * 68 + (tx << 2)];
            float a[4] = {a4.x, a4.y, a4.z, a4.w};
            float k4[4] = {b4.x, b4.y, b4.z, b4.w};
#pragma unroll
            for (int i = 0; i < 4; ++i)
#pragma unroll
                for (int j = 0; j < 4; ++j)
                    s[i][j] = fmaf(a[i], k4[j], s[i][j]);
        }

        // Online softmax per row (row spread over 16 tx lanes = half-warp)
#pragma unroll
        for (int i = 0; i < 4; ++i) {
            float rmax = fmaxf(fmaxf(s[i][0], s[i][1]), fmaxf(s[i][2], s[i][3]));
#pragma unroll
            for (int off = 8; off > 0; off >>= 1)
                rmax = fmaxf(rmax, __shfl_xor_sync(0xffffffffu, rmax, off));
            float mnew  = fmaxf(m[i], rmax);
            float alpha = __expf(m[i] - mnew);
            float p0 = __expf(s[i][0] - mnew);
            float p1 = __expf(s[i][1] - mnew);
            float p2 = __expf(s[i][2] - mnew);
            float p3 = __expf(s[i][3] - mnew);
            float psum = (p0 + p1) + (p2 + p3);
#pragma unroll
            for (int off = 8; off > 0; off >>= 1)
                psum += __shfl_xor_sync(0xffffffffu, psum, off);
            l[i] = l[i] * alpha + psum;
            m[i] = mnew;
            o[i][0] *= alpha; o[i][1] *= alpha; o[i][2] *= alpha; o[i][3] *= alpha;
            *(float4*)&ps[((ty << 2) + i) * 68 + (tx << 2)] =
                make_float4(p0, p1, p2, p3);
        }
        __syncthreads();

        // O += P @ V  (a: broadcast scalar reads, b: float4)
#pragma unroll 16
        for (int j = 0; j < 64; ++j) {
            float4 v4 = *(const float4*)&vs[j * 68 + (tx << 2)];
            float vv[4] = {v4.x, v4.y, v4.z, v4.w};
            float a0 = ps[((ty << 2) + 0) * 68 + j];
            float a1 = ps[((ty << 2) + 1) * 68 + j];
            float a2 = ps[((ty << 2) + 2) * 68 + j];
            float a3 = ps[((ty << 2) + 3) * 68 + j];
#pragma unroll
            for (int c = 0; c < 4; ++c) {
                o[0][c] = fmaf(a0, vv[c], o[0][c]);
                o[1][c] = fmaf(a1, vv[c], o[1][c]);
                o[2][c] = fmaf(a2, vv[c], o[2][c]);
                o[3][c] = fmaf(a3, vv[c], o[3][c]);
            }
        }
    }

    // Finalize: divide by l, write context (B,S,H,hd) flattened as (B,S,D)
#pragma unroll
    for (int i = 0; i < 4; ++i) {
        float inv = 1.0f / l[i];
        float4 ov = make_float4(o[i][0] * inv, o[i][1] * inv,
                                o[i][2] * inv, o[i][3] * inv);
        *(float4*)&ctx[(size_t)(b * SEQ + (ty << 2) + i) * DD + h * HDIM + (tx << 2)] = ov;
    }
}

// ---------------------------------------------------------------------------
// Circular-buffer store: new_bank[r] = memory_flat[(r-ptr) mod M] if that
// index < NQROWS, else memory_bank[r]. ptr is read device-side.
// ---------------------------------------------------------------------------
__global__ __launch_bounds__(256) void bank_update_kernel(
    const float* __restrict__ bank, const float* __restrict__ mem,
    const int* __restrict__ pptr, float* __restrict__ outb)
{
    int idx = blockIdx.x * blockDim.x + threadIdx.x;  // float4 index
    int r   = idx >> 7;           // DD/4 = 128 float4 per row
    int c   = (idx & 127) << 2;
    int ptr = *pptr;
    unsigned dd = (unsigned)(r - ptr) & (MBANK - 1);  // M is a power of two
    float4 v;
    if (dd < (unsigned)NQROWS)
        v = *(const float4*)&mem[(size_t)dd * DD + c];
    else
        v = *(const float4*)&bank[(size_t)r * DD + c];
    *(float4*)&outb[(size_t)r * DD + c] = v;
}

// ---------------------------------------------------------------------------
extern "C" void kernel_launch(void* const* d_in, const int* in_sizes, int n_in,
                              void* d_out, int out_size)
{
    const float* query  = (const float*)d_in[0];
    const float* memory = (const float*)d_in[1];
    const float* bank   = (const float*)d_in[2];
    const float* w_in   = (const float*)d_in[3];
    const float* b_in   = (const float*)d_in[4];
    const float* w_out  = (const float*)d_in[5];
    const float* b_out  = (const float*)d_in[6];
    const int*   pptr   = (const int*)d_in[7];

    float* out      = (float*)d_out;
    float* out_bank = out + (size_t)NQROWS * DD;

    float *gq, *gkv, *gctx;
    cudaGetSymbolAddress((void**)&gq,  g_q);
    cudaGetSymbolAddress((void**)&gkv, g_kv);
    cudaGetSymbolAddress((void**)&gctx, g_ctx);

    const int attn_smem = 4 * 64 * 68 * (int)sizeof(float);  // 69632 B
    cudaFuncSetAttribute(attn_kernel,
                         cudaFuncAttributeMaxDynamicSharedMemorySize, attn_smem);

    dim3 blk(256);

    // q = query @ Wq^T + bq        (2048 x 512)
    gemm_bias_kernel<<<dim3(DD / 64, NQROWS / 64), blk>>>(
        query, w_in, b_in, gq, NQROWS, DD, DD);

    // [k|v] = bank @ [Wk;Wv]^T + b (8192 x 1024)
    gemm_bias_kernel<<<dim3(1024 / 64, MBANK / 64), blk>>>(
        bank, w_in + (size_t)DD * DD, b_in + DD, gkv, MBANK, 1024, DD);

    // attention context (2048 x 512)
    attn_kernel<<<BATCH * NHEAD, blk, attn_smem>>>(gq, gkv, gctx);

    // retrieved = ctx @ Wo^T + bo  -> first NQROWS*DD of output
    gemm_bias_kernel<<<dim3(DD / 64, NQROWS / 64), blk>>>(
        gctx, w_out, b_out, out, NQROWS, DD, DD);

    // new_bank -> second MBANK*DD of output
    bank_update_kernel<<<(MBANK * DD / 4) / 256, blk>>>(
        bank, memory, pptr, out_bank);
}